// round 11
// baseline (speedup 1.0000x reference)
#include <cuda_runtime.h>
#include <cuda_fp16.h>
#include <math.h>

// IDXST_IDCT 4096x4096, half-length Hermitian FFT per row; fp16 intermediates.
//   A[m] = FFT_N(x * expk);  idct = Re A, idxst = Im A.
//   d[k] = 0.5*expk[k]*(X[k]+j X[N-k]) (MODE0) / -(X[N-k]+j X[k]) (MODE1)
//   E=d[k]+d[k+H], O=(d[k]-d[k+H])*W_N^k, z=E+jO, Z=FFT_H(z)
//   u[2n]=Re Z[n], u[2n+1]=Im Z[n];  expk[k+H]=expk[k]*e^{-j pi/4};
//   W_N^k via incremental recurrence W_N^{k+128} = W_N^k * e^{-j pi/16}.
// MODE0 (fp32 in) stages the row in smem (single DRAM read);
// MODE1 (fp16 in) reads the 4 Hermitian streams directly (cheap bytes).
// Pipeline: rowK(x fp32, expkN) -> half -> T(h->h) -> rowK(half, expkM) -> half -> T(h->f32)

#define LROW 4096
#define HN 2048
#define FFT_T 128
#define PADSZ (HN + HN / 16)  // 2176 float2 slots (17408 B)

__device__ float2 g_tA[128];  // W_2048^t
__device__ float2 g_tB[8];    // W_128^p
__device__ __half g_bufh0[(size_t)LROW * LROW];
__device__ __half g_bufh1[(size_t)LROW * LROW];

struct __align__(8) H4 { __half2 lo, hi; };
struct __align__(16) H8 { H4 a, b; };

__device__ __forceinline__ float2 cmul(float2 a, float2 b) {
    return make_float2(a.x * b.x - a.y * b.y, a.x * b.y + a.y * b.x);
}
__device__ __forceinline__ float2 cadd(float2 a, float2 b) {
    return make_float2(a.x + b.x, a.y + b.y);
}
__device__ __forceinline__ float2 csub(float2 a, float2 b) {
    return make_float2(a.x - b.x, a.y - b.y);
}

// e^{-2pi j k/16}, k=0..9
__constant__ float2 c_tw16[10] = {
    {1.f, 0.f},
    {0.92387953251128674f, -0.38268343236508978f},
    {0.70710678118654757f, -0.70710678118654757f},
    {0.38268343236508978f, -0.92387953251128674f},
    {0.f, -1.f},
    {-0.38268343236508978f, -0.92387953251128674f},
    {-0.70710678118654757f, -0.70710678118654757f},
    {-0.92387953251128674f, -0.38268343236508978f},
    {-1.f, 0.f},
    {-0.92387953251128674f, 0.38268343236508978f}};

__global__ void init_twiddles_kernel() {
    int t = threadIdx.x;  // 136 threads
    double s, c;
    if (t < 128) {
        sincospi(-(double)t / 1024.0, &s, &c);
        g_tA[t] = make_float2((float)c, (float)s);
    } else {
        int p = t - 128;
        sincospi(-(double)p / 64.0, &s, &c);
        g_tB[p] = make_float2((float)c, (float)s);
    }
}

// 16-point DFT, natural in/out (two radix-4 Stockham stages in regs).
__device__ __forceinline__ void fft16(float2 r[16]) {
    float2 y[16];
#pragma unroll
    for (int p = 0; p < 4; p++) {
        float2 a = r[p], b = r[p + 4], c = r[p + 8], d = r[p + 12];
        float2 apc = cadd(a, c), amc = csub(a, c);
        float2 bpd = cadd(b, d), bmd = csub(b, d);
        float2 jb = make_float2(-bmd.y, bmd.x);
        float2 o0 = cadd(apc, bpd);
        float2 o1 = csub(amc, jb);
        float2 o2 = csub(apc, bpd);
        float2 o3 = cadd(amc, jb);
        y[4 * p + 0] = o0;
        y[4 * p + 1] = (p == 0) ? o1 : cmul(o1, c_tw16[p]);
        y[4 * p + 2] = (p == 0) ? o2 : cmul(o2, c_tw16[2 * p]);
        y[4 * p + 3] = (p == 0) ? o3 : cmul(o3, c_tw16[3 * p]);
    }
#pragma unroll
    for (int q = 0; q < 4; q++) {
        float2 a = y[q], b = y[q + 4], c = y[q + 8], d = y[q + 12];
        float2 apc = cadd(a, c), amc = csub(a, c);
        float2 bpd = cadd(b, d), bmd = csub(b, d);
        float2 jb = make_float2(-bmd.y, bmd.x);
        r[q] = cadd(apc, bpd);
        r[q + 4] = csub(amc, jb);
        r[q + 8] = csub(apc, bpd);
        r[q + 12] = cadd(amc, jb);
    }
}

// 8-point DFT on x[0],x[2],...,x[14] (stride 2), in-place, natural order.
__device__ __forceinline__ void fft8_strided(float2* x) {
    float2 x0 = x[0], x1 = x[2], x2 = x[4], x3 = x[6];
    float2 x4 = x[8], x5 = x[10], x6 = x[12], x7 = x[14];
    float2 apc = cadd(x0, x4), amc = csub(x0, x4);
    float2 bpd = cadd(x2, x6), bmd = csub(x2, x6);
    float2 jb = make_float2(-bmd.y, bmd.x);
    float2 e0 = cadd(apc, bpd), e1 = csub(amc, jb);
    float2 e2 = csub(apc, bpd), e3 = cadd(amc, jb);
    apc = cadd(x1, x5); amc = csub(x1, x5);
    bpd = cadd(x3, x7); bmd = csub(x3, x7);
    jb = make_float2(-bmd.y, bmd.x);
    float2 o0 = cadd(apc, bpd), o1 = csub(amc, jb);
    float2 o2 = csub(apc, bpd), o3 = cadd(amc, jb);
    const float s = 0.70710678118654757f;
    float2 w1o = make_float2(s * (o1.x + o1.y), s * (o1.y - o1.x));
    float2 w2o = make_float2(o2.y, -o2.x);
    float2 w3o = make_float2(s * (o3.y - o3.x), -s * (o3.x + o3.y));
    x[0] = cadd(e0, o0);  x[8] = csub(e0, o0);
    x[2] = cadd(e1, w1o); x[10] = csub(e1, w1o);
    x[4] = cadd(e2, w2o); x[12] = csub(e2, w2o);
    x[6] = cadd(e3, w3o); x[14] = csub(e3, w3o);
}

// Store r[i]*w^i to dst[i*stride] with a depth-4 twiddle power tree.
__device__ __forceinline__ void twiddle_store(float2* dst, int stride,
                                              const float2 r[16], float2 w1) {
    float2 w2 = cmul(w1, w1);
    float2 w3 = cmul(w2, w1);
    float2 w4 = cmul(w2, w2);
    float2 w8 = cmul(w4, w4);
    dst[0] = r[0];
    dst[1 * stride] = cmul(r[1], w1);
    dst[2 * stride] = cmul(r[2], w2);
    dst[3 * stride] = cmul(r[3], w3);
    dst[4 * stride] = cmul(r[4], w4);
    dst[5 * stride] = cmul(r[5], cmul(w4, w1));
    dst[6 * stride] = cmul(r[6], cmul(w4, w2));
    dst[7 * stride] = cmul(r[7], cmul(w4, w3));
    dst[8 * stride] = cmul(r[8], w8);
    dst[9 * stride] = cmul(r[9], cmul(w8, w1));
    dst[10 * stride] = cmul(r[10], cmul(w8, w2));
    dst[11 * stride] = cmul(r[11], cmul(w8, w3));
    dst[12 * stride] = cmul(r[12], cmul(w8, w4));
    dst[13 * stride] = cmul(r[13], cmul(w8, cmul(w4, w1)));
    dst[14 * stride] = cmul(r[14], cmul(w8, cmul(w4, w2)));
    dst[15 * stride] = cmul(r[15], cmul(w8, cmul(w4, w3)));
}

// MODE 0: IDCT (u = Re A), fp32 input, smem-staged prologue.
// MODE 1: IDXST (u = Im A, se negated), fp16 input, direct-gmem prologue.
template <int MODE, bool HALF_IN>
__global__ __launch_bounds__(FFT_T, 8) void fft_row_kernel(
    const void* __restrict__ in_, const float2* __restrict__ expk,
    __half* __restrict__ out) {
    extern __shared__ float2 sm2[];
    float* sraw = reinterpret_cast<float*>(sm2);
    const int t = threadIdx.x;
    const size_t row = blockIdx.x;

    const float* __restrict__ inF = (const float*)in_ + row * LROW;
    const __half* __restrict__ inH = (const __half*)in_ + row * LROW;

    if (!HALF_IN) {  // stage fp32 row once, coalesced
        const float4* __restrict__ x4 = reinterpret_cast<const float4*>(inF);
        float4* s4 = reinterpret_cast<float4*>(sraw);
#pragma unroll
        for (int i = 0; i < 8; i++) s4[t + 128 * i] = x4[t + 128 * i];
        __syncthreads();
    }

    const float2 C8 = make_float2(0.70710678118654757f, -0.70710678118654757f);
    const float2 W16S = make_float2(0.98078528040323044f, -0.19509032201612827f);
    float2 r[16];
    float2 w4k;
#pragma unroll
    for (int i = 0; i < 16; i++) {
        const int k = t + 128 * i;  // k < 2048
        const int kb = (LROW - k) & (LROW - 1);
        float a, b, a2, b2;
        if (HALF_IN) {
            a = __half2float(inH[k]);
            b = __half2float(inH[kb]);
            a2 = __half2float(inH[k + HN]);
            b2 = __half2float(inH[HN - k]);
        } else {
            a = sraw[k];
            b = sraw[kb];
            a2 = sraw[k + HN];
            b2 = sraw[HN - k];
        }
        float2 e = expk[k];
        float2 e2 = cmul(e, C8);  // expk[k+2048]
        if (i == 0) {
            float2 esq = cmul(e, e);
            w4k = cmul(esq, esq);  // W_4096^k
        } else {
            w4k = cmul(w4k, W16S);
        }
        float2 v1, v2;
        if (MODE == 0) {
            v1 = make_float2(a, b);
            v2 = make_float2(a2, b2);
        } else {
            v1 = make_float2(-b, -a);
            v2 = make_float2(-b2, -a2);
        }
        float2 dk = cmul(e, v1);
        float2 dk2 = cmul(e2, v2);
        if (k == 0) dk = make_float2(MODE == 0 ? 2.f * a : 0.f, 0.f);
        float2 E = cadd(dk, dk2);
        float2 Od = csub(dk, dk2);
        float2 O = cmul(Od, w4k);
        r[i] = make_float2(E.x - O.y, E.y + O.x);  // z = E + j*O
    }
    if (!HALF_IN) __syncthreads();  // sraw reads done before workspace writes

    // ---- FFT_2048, Stockham radix 16*16*8, 128 threads x 16 regs ----
    fft16(r);
    twiddle_store(&sm2[17 * t], 1, r, g_tA[t]);
    __syncthreads();
    const int rb = t + (t >> 4);
#pragma unroll
    for (int i = 0; i < 16; i++) r[i] = sm2[rb + 136 * i];  // X[t+128i]
    __syncthreads();

    fft16(r);
    twiddle_store(&sm2[(t & 15) + 272 * (t >> 4)], 17, r, g_tB[t >> 4]);
    __syncthreads();
#pragma unroll
    for (int i = 0; i < 16; i++) r[i] = sm2[rb + 136 * i];
    __syncthreads();

    fft8_strided(&r[0]);
    fft8_strided(&r[1]);

    // Z[t+256i] = r[2i], Z[t+128+256i] = r[2i+1]; store padded.
#pragma unroll
    for (int i = 0; i < 8; i++) {
        int ra = t + 256 * i;
        sm2[ra + (ra >> 4)] = r[2 * i];
        int rbb = t + 128 + 256 * i;
        sm2[rbb + (rbb >> 4)] = r[2 * i + 1];
    }
    __syncthreads();

    // out[8c..8c+7] built from Z[2c], Z[2c+1], Z[2047-2c], Z[2046-2c]; one STG.128.
    const float se = (MODE == 0) ? 0.5f : -0.5f;
    H8* __restrict__ o8 = reinterpret_cast<H8*>(out + row * LROW);
#pragma unroll
    for (int jj = 0; jj < 4; jj++) {
        int c = t + 128 * jj;  // c < 512
        int m0 = 2 * c, m1 = 2 * c + 1;
        int mr0 = 2047 - 2 * c, mr1 = 2046 - 2 * c;
        float2 z0 = sm2[m0 + (m0 >> 4)];
        float2 z1 = sm2[m1 + (m1 >> 4)];
        float2 zr0 = sm2[mr0 + (mr0 >> 4)];
        float2 zr1 = sm2[mr1 + (mr1 >> 4)];
        H8 h;
        h.a.lo = __floats2half2_rn(se * z0.x, 0.5f * zr0.y);
        h.a.hi = __floats2half2_rn(se * z0.y, 0.5f * zr0.x);
        h.b.lo = __floats2half2_rn(se * z1.x, 0.5f * zr1.y);
        h.b.hi = __floats2half2_rn(se * z1.y, 0.5f * zr1.x);
        o8[c] = h;
    }
}

// 64x64 half transpose, 128 threads, 4 batched uint4 loads/thread for MLP.
// OUT_FLOAT: convert to fp32 on store (final pass).
template <bool OUT_FLOAT>
__global__ __launch_bounds__(128) void transpose_h_kernel(
    const __half* __restrict__ in, void* __restrict__ out_) {
    __shared__ __half tile[64][65];
    const int x0 = blockIdx.x * 64, y0 = blockIdx.y * 64;
    const int tx = threadIdx.x & 7;   // 0..7
    const int ty = threadIdx.x >> 3;  // 0..15

    uint4 u[4];
#pragma unroll
    for (int j = 0; j < 4; j++) {
        int r = ty + 16 * j;
        u[j] = *reinterpret_cast<const uint4*>(&in[(size_t)(y0 + r) * LROW + x0 + 8 * tx]);
    }
#pragma unroll
    for (int j = 0; j < 4; j++) {
        int r = ty + 16 * j;
        __half tmp[8];
        *reinterpret_cast<uint4*>(tmp) = u[j];
#pragma unroll
        for (int q = 0; q < 8; q++) tile[8 * tx + q][r] = tmp[q];
    }
    __syncthreads();

#pragma unroll
    for (int j = 0; j < 4; j++) {
        int c = ty + 16 * j;  // out row = x0 + c, cols y0 + 8tx .. +7
        if (OUT_FLOAT) {
            float* out = (float*)out_;
            float4 v0, v1;
            v0.x = __half2float(tile[c][8 * tx + 0]);
            v0.y = __half2float(tile[c][8 * tx + 1]);
            v0.z = __half2float(tile[c][8 * tx + 2]);
            v0.w = __half2float(tile[c][8 * tx + 3]);
            v1.x = __half2float(tile[c][8 * tx + 4]);
            v1.y = __half2float(tile[c][8 * tx + 5]);
            v1.z = __half2float(tile[c][8 * tx + 6]);
            v1.w = __half2float(tile[c][8 * tx + 7]);
            float4* o = reinterpret_cast<float4*>(&out[(size_t)(x0 + c) * LROW + y0 + 8 * tx]);
            o[0] = v0;
            o[1] = v1;
        } else {
            __half* out = (__half*)out_;
            __half tmp[8];
#pragma unroll
            for (int q = 0; q < 8; q++) tmp[q] = tile[c][8 * tx + q];
            *reinterpret_cast<uint4*>(&out[(size_t)(x0 + c) * LROW + y0 + 8 * tx]) =
                *reinterpret_cast<uint4*>(tmp);
        }
    }
}

extern "C" void kernel_launch(void* const* d_in, const int* in_sizes, int n_in,
                              void* d_out, int out_size) {
    const float* x = (const float*)d_in[0];
    const float2* expkM = (const float2*)d_in[1];
    const float2* expkN = (const float2*)d_in[2];
    float* out = (float*)d_out;

    __half *bh0, *bh1;
    cudaGetSymbolAddress((void**)&bh0, g_bufh0);
    cudaGetSymbolAddress((void**)&bh1, g_bufh1);

    const size_t smem = (size_t)PADSZ * sizeof(float2);  // 17408 B
    dim3 tg(64, 64);

    init_twiddles_kernel<<<1, 136>>>();
    fft_row_kernel<0, false><<<LROW, FFT_T, smem>>>(x, expkN, bh0);   // t (fp16)
    transpose_h_kernel<false><<<tg, 128>>>(bh0, bh1);                 // t^T (fp16)
    fft_row_kernel<1, true><<<LROW, FFT_T, smem>>>(bh1, expkM, bh0);  // y^T (fp16)
    transpose_h_kernel<true><<<tg, 128>>>(bh0, out);                  // y (fp32)
}

// round 12
// speedup vs baseline: 1.4899x; 1.4899x over previous
#include <cuda_runtime.h>
#include <cuda_fp16.h>
#include <math.h>

// IDXST_IDCT 4096x4096, half-length Hermitian FFT per row; fp16 intermediates.
//   A[m] = FFT_N(x * expk);  idct = Re A, idxst = Im A.
//   d[k] = 0.5*expk[k]*(X[k]+j X[N-k]) (MODE0) / -(X[N-k]+j X[k]) (MODE1)
//   E=d[k]+d[k+H], O=(d[k]-d[k+H])*W_N^k, z=E+jO, Z=FFT_H(z)
//   u[2n]=Re Z[n], u[2n+1]=Im Z[n];  expk[k+H]=expk[k]*e^{-j pi/4};
//   W_N^k via incremental recurrence W_N^{k+128} = W_N^k * e^{-j pi/16}.
// MODE0 (fp32 in): smem-staged prologue (single DRAM read of the row).
// MODE1 (fp16 in): direct-gmem Hermitian streams (cheap bytes, fewer instrs).
// Epilogue: flat H4 stores, stride-1 conflict-free smem reads (R9-verified).
// Pipeline: rowK(x fp32, expkN) -> half -> T(h->h) -> rowK(half, expkM) -> half -> T(h->f32)

#define LROW 4096
#define HN 2048
#define FFT_T 128
#define PADSZ (HN + HN / 16)  // 2176 float2 slots (17408 B)

__device__ float2 g_tA[128];  // W_2048^t
__device__ float2 g_tB[8];    // W_128^p
__device__ __half g_bufh0[(size_t)LROW * LROW];
__device__ __half g_bufh1[(size_t)LROW * LROW];

struct __align__(8) H4 { __half2 lo, hi; };

__device__ __forceinline__ float2 cmul(float2 a, float2 b) {
    return make_float2(a.x * b.x - a.y * b.y, a.x * b.y + a.y * b.x);
}
__device__ __forceinline__ float2 cadd(float2 a, float2 b) {
    return make_float2(a.x + b.x, a.y + b.y);
}
__device__ __forceinline__ float2 csub(float2 a, float2 b) {
    return make_float2(a.x - b.x, a.y - b.y);
}

// e^{-2pi j k/16}, k=0..9
__constant__ float2 c_tw16[10] = {
    {1.f, 0.f},
    {0.92387953251128674f, -0.38268343236508978f},
    {0.70710678118654757f, -0.70710678118654757f},
    {0.38268343236508978f, -0.92387953251128674f},
    {0.f, -1.f},
    {-0.38268343236508978f, -0.92387953251128674f},
    {-0.70710678118654757f, -0.70710678118654757f},
    {-0.92387953251128674f, -0.38268343236508978f},
    {-1.f, 0.f},
    {-0.92387953251128674f, 0.38268343236508978f}};

__global__ void init_twiddles_kernel() {
    int t = threadIdx.x;  // 136 threads
    double s, c;
    if (t < 128) {
        sincospi(-(double)t / 1024.0, &s, &c);
        g_tA[t] = make_float2((float)c, (float)s);
    } else {
        int p = t - 128;
        sincospi(-(double)p / 64.0, &s, &c);
        g_tB[p] = make_float2((float)c, (float)s);
    }
}

// 16-point DFT, natural in/out (two radix-4 Stockham stages in regs).
__device__ __forceinline__ void fft16(float2 r[16]) {
    float2 y[16];
#pragma unroll
    for (int p = 0; p < 4; p++) {
        float2 a = r[p], b = r[p + 4], c = r[p + 8], d = r[p + 12];
        float2 apc = cadd(a, c), amc = csub(a, c);
        float2 bpd = cadd(b, d), bmd = csub(b, d);
        float2 jb = make_float2(-bmd.y, bmd.x);
        float2 o0 = cadd(apc, bpd);
        float2 o1 = csub(amc, jb);
        float2 o2 = csub(apc, bpd);
        float2 o3 = cadd(amc, jb);
        y[4 * p + 0] = o0;
        y[4 * p + 1] = (p == 0) ? o1 : cmul(o1, c_tw16[p]);
        y[4 * p + 2] = (p == 0) ? o2 : cmul(o2, c_tw16[2 * p]);
        y[4 * p + 3] = (p == 0) ? o3 : cmul(o3, c_tw16[3 * p]);
    }
#pragma unroll
    for (int q = 0; q < 4; q++) {
        float2 a = y[q], b = y[q + 4], c = y[q + 8], d = y[q + 12];
        float2 apc = cadd(a, c), amc = csub(a, c);
        float2 bpd = cadd(b, d), bmd = csub(b, d);
        float2 jb = make_float2(-bmd.y, bmd.x);
        r[q] = cadd(apc, bpd);
        r[q + 4] = csub(amc, jb);
        r[q + 8] = csub(apc, bpd);
        r[q + 12] = cadd(amc, jb);
    }
}

// 8-point DFT on x[0],x[2],...,x[14] (stride 2), in-place, natural order.
__device__ __forceinline__ void fft8_strided(float2* x) {
    float2 x0 = x[0], x1 = x[2], x2 = x[4], x3 = x[6];
    float2 x4 = x[8], x5 = x[10], x6 = x[12], x7 = x[14];
    float2 apc = cadd(x0, x4), amc = csub(x0, x4);
    float2 bpd = cadd(x2, x6), bmd = csub(x2, x6);
    float2 jb = make_float2(-bmd.y, bmd.x);
    float2 e0 = cadd(apc, bpd), e1 = csub(amc, jb);
    float2 e2 = csub(apc, bpd), e3 = cadd(amc, jb);
    apc = cadd(x1, x5); amc = csub(x1, x5);
    bpd = cadd(x3, x7); bmd = csub(x3, x7);
    jb = make_float2(-bmd.y, bmd.x);
    float2 o0 = cadd(apc, bpd), o1 = csub(amc, jb);
    float2 o2 = csub(apc, bpd), o3 = cadd(amc, jb);
    const float s = 0.70710678118654757f;
    float2 w1o = make_float2(s * (o1.x + o1.y), s * (o1.y - o1.x));
    float2 w2o = make_float2(o2.y, -o2.x);
    float2 w3o = make_float2(s * (o3.y - o3.x), -s * (o3.x + o3.y));
    x[0] = cadd(e0, o0);  x[8] = csub(e0, o0);
    x[2] = cadd(e1, w1o); x[10] = csub(e1, w1o);
    x[4] = cadd(e2, w2o); x[12] = csub(e2, w2o);
    x[6] = cadd(e3, w3o); x[14] = csub(e3, w3o);
}

// Store r[i]*w^i to dst[i*stride] with a depth-4 twiddle power tree.
__device__ __forceinline__ void twiddle_store(float2* dst, int stride,
                                              const float2 r[16], float2 w1) {
    float2 w2 = cmul(w1, w1);
    float2 w3 = cmul(w2, w1);
    float2 w4 = cmul(w2, w2);
    float2 w8 = cmul(w4, w4);
    dst[0] = r[0];
    dst[1 * stride] = cmul(r[1], w1);
    dst[2 * stride] = cmul(r[2], w2);
    dst[3 * stride] = cmul(r[3], w3);
    dst[4 * stride] = cmul(r[4], w4);
    dst[5 * stride] = cmul(r[5], cmul(w4, w1));
    dst[6 * stride] = cmul(r[6], cmul(w4, w2));
    dst[7 * stride] = cmul(r[7], cmul(w4, w3));
    dst[8 * stride] = cmul(r[8], w8);
    dst[9 * stride] = cmul(r[9], cmul(w8, w1));
    dst[10 * stride] = cmul(r[10], cmul(w8, w2));
    dst[11 * stride] = cmul(r[11], cmul(w8, w3));
    dst[12 * stride] = cmul(r[12], cmul(w8, w4));
    dst[13 * stride] = cmul(r[13], cmul(w8, cmul(w4, w1)));
    dst[14 * stride] = cmul(r[14], cmul(w8, cmul(w4, w2)));
    dst[15 * stride] = cmul(r[15], cmul(w8, cmul(w4, w3)));
}

// MODE 0: IDCT (u = Re A), fp32 input, smem-staged prologue.
// MODE 1: IDXST (u = Im A, se negated), fp16 input, direct-gmem prologue.
template <int MODE, bool HALF_IN>
__global__ __launch_bounds__(FFT_T, 8) void fft_row_kernel(
    const void* __restrict__ in_, const float2* __restrict__ expk,
    __half* __restrict__ out) {
    extern __shared__ float2 sm2[];
    float* sraw = reinterpret_cast<float*>(sm2);
    const int t = threadIdx.x;
    const size_t row = blockIdx.x;

    const float* __restrict__ inF = (const float*)in_ + row * LROW;
    const __half* __restrict__ inH = (const __half*)in_ + row * LROW;

    if (!HALF_IN) {  // stage fp32 row once, coalesced
        const float4* __restrict__ x4 = reinterpret_cast<const float4*>(inF);
        float4* s4 = reinterpret_cast<float4*>(sraw);
#pragma unroll
        for (int i = 0; i < 8; i++) s4[t + 128 * i] = x4[t + 128 * i];
        __syncthreads();
    }

    const float2 C8 = make_float2(0.70710678118654757f, -0.70710678118654757f);
    const float2 W16S = make_float2(0.98078528040323044f, -0.19509032201612827f);
    float2 r[16];
    float2 w4k;
#pragma unroll
    for (int i = 0; i < 16; i++) {
        const int k = t + 128 * i;  // k < 2048
        const int kb = (LROW - k) & (LROW - 1);
        float a, b, a2, b2;
        if (HALF_IN) {
            a = __half2float(inH[k]);
            b = __half2float(inH[kb]);
            a2 = __half2float(inH[k + HN]);
            b2 = __half2float(inH[HN - k]);
        } else {
            a = sraw[k];
            b = sraw[kb];
            a2 = sraw[k + HN];
            b2 = sraw[HN - k];
        }
        float2 e = expk[k];
        float2 e2 = cmul(e, C8);  // expk[k+2048]
        if (i == 0) {
            float2 esq = cmul(e, e);
            w4k = cmul(esq, esq);  // W_4096^k
        } else {
            w4k = cmul(w4k, W16S);
        }
        float2 v1, v2;
        if (MODE == 0) {
            v1 = make_float2(a, b);
            v2 = make_float2(a2, b2);
        } else {
            v1 = make_float2(-b, -a);
            v2 = make_float2(-b2, -a2);
        }
        float2 dk = cmul(e, v1);
        float2 dk2 = cmul(e2, v2);
        if (k == 0) dk = make_float2(MODE == 0 ? 2.f * a : 0.f, 0.f);
        float2 E = cadd(dk, dk2);
        float2 Od = csub(dk, dk2);
        float2 O = cmul(Od, w4k);
        r[i] = make_float2(E.x - O.y, E.y + O.x);  // z = E + j*O
    }
    if (!HALF_IN) __syncthreads();  // sraw reads done before workspace writes

    // ---- FFT_2048, Stockham radix 16*16*8, 128 threads x 16 regs ----
    fft16(r);
    twiddle_store(&sm2[17 * t], 1, r, g_tA[t]);
    __syncthreads();
    const int rb = t + (t >> 4);
#pragma unroll
    for (int i = 0; i < 16; i++) r[i] = sm2[rb + 136 * i];  // X[t+128i]
    __syncthreads();

    fft16(r);
    twiddle_store(&sm2[(t & 15) + 272 * (t >> 4)], 17, r, g_tB[t >> 4]);
    __syncthreads();
#pragma unroll
    for (int i = 0; i < 16; i++) r[i] = sm2[rb + 136 * i];
    __syncthreads();

    fft8_strided(&r[0]);
    fft8_strided(&r[1]);

    // Z[t+256i] = r[2i], Z[t+128+256i] = r[2i+1]; store padded.
#pragma unroll
    for (int i = 0; i < 8; i++) {
        int ra = t + 256 * i;
        sm2[ra + (ra >> 4)] = r[2 * i];
        int rbb = t + 128 + 256 * i;
        sm2[rbb + (rbb >> 4)] = r[2 * i + 1];
    }
    __syncthreads();

    // out[4c..4c+3] = (se*ReZ[c], 0.5*ImZ[2047-c], se*ImZ[c], 0.5*ReZ[2047-c]) as fp16
    const float se = (MODE == 0) ? 0.5f : -0.5f;
    H4* __restrict__ o4 = reinterpret_cast<H4*>(out + row * LROW);
#pragma unroll
    for (int jj = 0; jj < 8; jj++) {
        int c = t + 128 * jj;  // c < 1024
        float2 zc = sm2[c + (c >> 4)];
        int cr = 2047 - c;
        float2 zr = sm2[cr + (cr >> 4)];
        H4 h;
        h.lo = __floats2half2_rn(se * zc.x, 0.5f * zr.y);
        h.hi = __floats2half2_rn(se * zc.y, 0.5f * zr.x);
        o4[c] = h;
    }
}

// 64x64 half transpose, 128 threads, 4 batched uint4 loads/thread for MLP.
// OUT_FLOAT: convert to fp32 on store (final pass).
template <bool OUT_FLOAT>
__global__ __launch_bounds__(128) void transpose_h_kernel(
    const __half* __restrict__ in, void* __restrict__ out_) {
    __shared__ __half tile[64][65];
    const int x0 = blockIdx.x * 64, y0 = blockIdx.y * 64;
    const int tx = threadIdx.x & 7;   // 0..7
    const int ty = threadIdx.x >> 3;  // 0..15

    uint4 u[4];
#pragma unroll
    for (int j = 0; j < 4; j++) {
        int r = ty + 16 * j;
        u[j] = *reinterpret_cast<const uint4*>(&in[(size_t)(y0 + r) * LROW + x0 + 8 * tx]);
    }
#pragma unroll
    for (int j = 0; j < 4; j++) {
        int r = ty + 16 * j;
        __half tmp[8];
        *reinterpret_cast<uint4*>(tmp) = u[j];
#pragma unroll
        for (int q = 0; q < 8; q++) tile[8 * tx + q][r] = tmp[q];
    }
    __syncthreads();

#pragma unroll
    for (int j = 0; j < 4; j++) {
        int c = ty + 16 * j;  // out row = x0 + c, cols y0 + 8tx .. +7
        if (OUT_FLOAT) {
            float* out = (float*)out_;
            float4 v0, v1;
            v0.x = __half2float(tile[c][8 * tx + 0]);
            v0.y = __half2float(tile[c][8 * tx + 1]);
            v0.z = __half2float(tile[c][8 * tx + 2]);
            v0.w = __half2float(tile[c][8 * tx + 3]);
            v1.x = __half2float(tile[c][8 * tx + 4]);
            v1.y = __half2float(tile[c][8 * tx + 5]);
            v1.z = __half2float(tile[c][8 * tx + 6]);
            v1.w = __half2float(tile[c][8 * tx + 7]);
            float4* o = reinterpret_cast<float4*>(&out[(size_t)(x0 + c) * LROW + y0 + 8 * tx]);
            o[0] = v0;
            o[1] = v1;
        } else {
            __half* out = (__half*)out_;
            __half tmp[8];
#pragma unroll
            for (int q = 0; q < 8; q++) tmp[q] = tile[c][8 * tx + q];
            *reinterpret_cast<uint4*>(&out[(size_t)(x0 + c) * LROW + y0 + 8 * tx]) =
                *reinterpret_cast<uint4*>(tmp);
        }
    }
}

extern "C" void kernel_launch(void* const* d_in, const int* in_sizes, int n_in,
                              void* d_out, int out_size) {
    const float* x = (const float*)d_in[0];
    const float2* expkM = (const float2*)d_in[1];
    const float2* expkN = (const float2*)d_in[2];
    float* out = (float*)d_out;

    __half *bh0, *bh1;
    cudaGetSymbolAddress((void**)&bh0, g_bufh0);
    cudaGetSymbolAddress((void**)&bh1, g_bufh1);

    const size_t smem = (size_t)PADSZ * sizeof(float2);  // 17408 B
    dim3 tg(64, 64);

    init_twiddles_kernel<<<1, 136>>>();
    fft_row_kernel<0, false><<<LROW, FFT_T, smem>>>(x, expkN, bh0);   // t (fp16)
    transpose_h_kernel<false><<<tg, 128>>>(bh0, bh1);                 // t^T (fp16)
    fft_row_kernel<1, true><<<LROW, FFT_T, smem>>>(bh1, expkM, bh0);  // y^T (fp16)
    transpose_h_kernel<true><<<tg, 128>>>(bh0, out);                  // y (fp32)
}

// round 13
// speedup vs baseline: 1.5947x; 1.0703x over previous
#include <cuda_runtime.h>
#include <cuda_fp16.h>
#include <math.h>

// IDXST_IDCT 4096x4096, half-length Hermitian FFT per row; fp16 intermediates.
//   A[m] = FFT_N(x * expk);  idct = Re A, idxst = Im A.
//   d[k] = 0.5*expk[k]*(X[k]+j X[N-k]) (MODE0) / -(X[N-k]+j X[k]) (MODE1)
//   E=d[k]+d[k+H], O=(d[k]-d[k+H])*W_N^k, z=E+jO, Z=FFT_H(z)
//   u[2n]=Re Z[n], u[2n+1]=Im Z[n];  expk[k+H]=expk[k]*e^{-j pi/4}; W_N^k=expk[k]^4.
// Final stage computes butterflies q=t (even regs) and q'=255-t (odd regs) so each
// thread owns both Z[c] and Z[2047-c] -> epilogue entirely in registers (no smem).
// Pipeline: rowK(x fp32, expkN) -> half -> T(h->h) -> rowK(half, expkM) -> half -> T(h->f32)

#define LROW 4096
#define HN 2048
#define FFT_T 128
#define PADSZ (HN + HN / 16)  // 2176 float2 slots (17408 B)

__device__ float2 g_tA[128];  // W_2048^t
__device__ float2 g_tB[8];    // W_128^p
__device__ __half g_bufh0[(size_t)LROW * LROW];
__device__ __half g_bufh1[(size_t)LROW * LROW];

struct __align__(8) H4 { __half2 lo, hi; };

__device__ __forceinline__ float2 cmul(float2 a, float2 b) {
    return make_float2(a.x * b.x - a.y * b.y, a.x * b.y + a.y * b.x);
}
__device__ __forceinline__ float2 cadd(float2 a, float2 b) {
    return make_float2(a.x + b.x, a.y + b.y);
}
__device__ __forceinline__ float2 csub(float2 a, float2 b) {
    return make_float2(a.x - b.x, a.y - b.y);
}

// e^{-2pi j k/16}, k=0..9
__constant__ float2 c_tw16[10] = {
    {1.f, 0.f},
    {0.92387953251128674f, -0.38268343236508978f},
    {0.70710678118654757f, -0.70710678118654757f},
    {0.38268343236508978f, -0.92387953251128674f},
    {0.f, -1.f},
    {-0.38268343236508978f, -0.92387953251128674f},
    {-0.70710678118654757f, -0.70710678118654757f},
    {-0.92387953251128674f, -0.38268343236508978f},
    {-1.f, 0.f},
    {-0.92387953251128674f, 0.38268343236508978f}};

__global__ void init_twiddles_kernel() {
    int t = threadIdx.x;  // 136 threads
    double s, c;
    if (t < 128) {
        sincospi(-(double)t / 1024.0, &s, &c);
        g_tA[t] = make_float2((float)c, (float)s);
    } else {
        int p = t - 128;
        sincospi(-(double)p / 64.0, &s, &c);
        g_tB[p] = make_float2((float)c, (float)s);
    }
}

// 16-point DFT, natural in/out (two radix-4 Stockham stages in regs).
__device__ __forceinline__ void fft16(float2 r[16]) {
    float2 y[16];
#pragma unroll
    for (int p = 0; p < 4; p++) {
        float2 a = r[p], b = r[p + 4], c = r[p + 8], d = r[p + 12];
        float2 apc = cadd(a, c), amc = csub(a, c);
        float2 bpd = cadd(b, d), bmd = csub(b, d);
        float2 jb = make_float2(-bmd.y, bmd.x);
        float2 o0 = cadd(apc, bpd);
        float2 o1 = csub(amc, jb);
        float2 o2 = csub(apc, bpd);
        float2 o3 = cadd(amc, jb);
        y[4 * p + 0] = o0;
        y[4 * p + 1] = (p == 0) ? o1 : cmul(o1, c_tw16[p]);
        y[4 * p + 2] = (p == 0) ? o2 : cmul(o2, c_tw16[2 * p]);
        y[4 * p + 3] = (p == 0) ? o3 : cmul(o3, c_tw16[3 * p]);
    }
#pragma unroll
    for (int q = 0; q < 4; q++) {
        float2 a = y[q], b = y[q + 4], c = y[q + 8], d = y[q + 12];
        float2 apc = cadd(a, c), amc = csub(a, c);
        float2 bpd = cadd(b, d), bmd = csub(b, d);
        float2 jb = make_float2(-bmd.y, bmd.x);
        r[q] = cadd(apc, bpd);
        r[q + 4] = csub(amc, jb);
        r[q + 8] = csub(apc, bpd);
        r[q + 12] = cadd(amc, jb);
    }
}

// 8-point DFT on x[0],x[2],...,x[14] (stride 2), in-place, natural order.
__device__ __forceinline__ void fft8_strided(float2* x) {
    float2 x0 = x[0], x1 = x[2], x2 = x[4], x3 = x[6];
    float2 x4 = x[8], x5 = x[10], x6 = x[12], x7 = x[14];
    float2 apc = cadd(x0, x4), amc = csub(x0, x4);
    float2 bpd = cadd(x2, x6), bmd = csub(x2, x6);
    float2 jb = make_float2(-bmd.y, bmd.x);
    float2 e0 = cadd(apc, bpd), e1 = csub(amc, jb);
    float2 e2 = csub(apc, bpd), e3 = cadd(amc, jb);
    apc = cadd(x1, x5); amc = csub(x1, x5);
    bpd = cadd(x3, x7); bmd = csub(x3, x7);
    jb = make_float2(-bmd.y, bmd.x);
    float2 o0 = cadd(apc, bpd), o1 = csub(amc, jb);
    float2 o2 = csub(apc, bpd), o3 = cadd(amc, jb);
    const float s = 0.70710678118654757f;
    float2 w1o = make_float2(s * (o1.x + o1.y), s * (o1.y - o1.x));
    float2 w2o = make_float2(o2.y, -o2.x);
    float2 w3o = make_float2(s * (o3.y - o3.x), -s * (o3.x + o3.y));
    x[0] = cadd(e0, o0);  x[8] = csub(e0, o0);
    x[2] = cadd(e1, w1o); x[10] = csub(e1, w1o);
    x[4] = cadd(e2, w2o); x[12] = csub(e2, w2o);
    x[6] = cadd(e3, w3o); x[14] = csub(e3, w3o);
}

// Store r[i]*w^i to dst[i*stride] with a depth-4 twiddle power tree.
__device__ __forceinline__ void twiddle_store(float2* dst, int stride,
                                              const float2 r[16], float2 w1) {
    float2 w2 = cmul(w1, w1);
    float2 w3 = cmul(w2, w1);
    float2 w4 = cmul(w2, w2);
    float2 w8 = cmul(w4, w4);
    dst[0] = r[0];
    dst[1 * stride] = cmul(r[1], w1);
    dst[2 * stride] = cmul(r[2], w2);
    dst[3 * stride] = cmul(r[3], w3);
    dst[4 * stride] = cmul(r[4], w4);
    dst[5 * stride] = cmul(r[5], cmul(w4, w1));
    dst[6 * stride] = cmul(r[6], cmul(w4, w2));
    dst[7 * stride] = cmul(r[7], cmul(w4, w3));
    dst[8 * stride] = cmul(r[8], w8);
    dst[9 * stride] = cmul(r[9], cmul(w8, w1));
    dst[10 * stride] = cmul(r[10], cmul(w8, w2));
    dst[11 * stride] = cmul(r[11], cmul(w8, w3));
    dst[12 * stride] = cmul(r[12], cmul(w8, w4));
    dst[13 * stride] = cmul(r[13], cmul(w8, cmul(w4, w1)));
    dst[14 * stride] = cmul(r[14], cmul(w8, cmul(w4, w2)));
    dst[15 * stride] = cmul(r[15], cmul(w8, cmul(w4, w3)));
}

// MODE 0: IDCT (u = Re A).  MODE 1: IDXST (u = Im A, se negated).
// HALF_IN: input matrix is fp16 (intermediate) vs fp32 (original x).
template <int MODE, bool HALF_IN>
__global__ __launch_bounds__(FFT_T, 8) void fft_row_kernel(
    const void* __restrict__ in_, const float2* __restrict__ expk,
    __half* __restrict__ out) {
    extern __shared__ float2 sm2[];
    float* sraw = reinterpret_cast<float*>(sm2);
    const int t = threadIdx.x;
    const size_t row = blockIdx.x;

    // Stage full row into smem as fp32, coalesced vector loads. (R9-verified)
    if (!HALF_IN) {
        const float4* __restrict__ x4 =
            reinterpret_cast<const float4*>((const float*)in_ + row * LROW);
        float4* s4 = reinterpret_cast<float4*>(sraw);
#pragma unroll
        for (int i = 0; i < 8; i++) s4[t + 128 * i] = x4[t + 128 * i];
    } else {
        const uint4* __restrict__ x4 =
            reinterpret_cast<const uint4*>((const __half*)in_ + row * LROW);
        float4* s4 = reinterpret_cast<float4*>(sraw);
#pragma unroll
        for (int i = 0; i < 4; i++) {
            uint4 u = x4[t + 128 * i];
            __half2 h[4];
            *reinterpret_cast<uint4*>(h) = u;
            float2 f0 = __half22float2(h[0]);
            float2 f1 = __half22float2(h[1]);
            float2 f2 = __half22float2(h[2]);
            float2 f3 = __half22float2(h[3]);
            s4[2 * (t + 128 * i)] = make_float4(f0.x, f0.y, f1.x, f1.y);
            s4[2 * (t + 128 * i) + 1] = make_float4(f2.x, f2.y, f3.x, f3.y);
        }
    }
    __syncthreads();

    const float2 C8 = make_float2(0.70710678118654757f, -0.70710678118654757f);
    float2 r[16];
#pragma unroll
    for (int i = 0; i < 16; i++) {
        const int k = t + 128 * i;  // k < 2048
        float a = sraw[k];
        float b = sraw[(LROW - k) & (LROW - 1)];
        float a2 = sraw[k + HN];
        float b2 = sraw[HN - k];
        float2 e = expk[k];
        float2 e2 = cmul(e, C8);      // expk[k+2048]
        float2 esq = cmul(e, e);
        float2 w4k = cmul(esq, esq);  // W_4096^k
        float2 v1, v2;
        if (MODE == 0) {
            v1 = make_float2(a, b);
            v2 = make_float2(a2, b2);
        } else {
            v1 = make_float2(-b, -a);
            v2 = make_float2(-b2, -a2);
        }
        float2 dk = cmul(e, v1);
        float2 dk2 = cmul(e2, v2);
        if (k == 0) dk = make_float2(MODE == 0 ? 2.f * a : 0.f, 0.f);
        float2 E = cadd(dk, dk2);
        float2 Od = csub(dk, dk2);
        float2 O = cmul(Od, w4k);
        r[i] = make_float2(E.x - O.y, E.y + O.x);  // z = E + j*O
    }
    __syncthreads();  // all sraw reads done before workspace writes

    // ---- FFT_2048, Stockham radix 16*16*8, 128 threads x 16 regs ----
    fft16(r);
    twiddle_store(&sm2[17 * t], 1, r, g_tA[t]);
    __syncthreads();
    const int rb = t + (t >> 4);
#pragma unroll
    for (int i = 0; i < 16; i++) r[i] = sm2[rb + 136 * i];  // X[t+128i]
    __syncthreads();

    fft16(r);
    twiddle_store(&sm2[(t & 15) + 272 * (t >> 4)], 17, r, g_tB[t >> 4]);
    __syncthreads();

    // Second exchange, re-assigned for the register epilogue:
    //   even regs r[2u]   = X[t + 256u]        (butterfly q  = t)
    //   odd  regs r[2u+1] = X[(255-t) + 256u]  (butterfly q' = 255-t)
    const int tr = 255 - t;
    const int rb2 = tr + (tr >> 4);
#pragma unroll
    for (int u = 0; u < 8; u++) {
        r[2 * u] = sm2[rb + 272 * u];
        r[2 * u + 1] = sm2[rb2 + 272 * u];
    }

    fft8_strided(&r[0]);  // -> r[2i]   = Z[t + 256i]
    fft8_strided(&r[1]);  // -> r[2i+1] = Z[(255-t) + 256i]

    // Epilogue entirely in registers. Quad c needs Z[c] and Z[2047-c]:
    //   c = t+256u     : Z[c]=r[2u],        Z[2047-c]=Z[(255-t)+256(7-u)]=r[2(7-u)+1]
    //   c = (255-t)+256v: Z[c]=r[2v+1],     Z[2047-c]=Z[t+256(7-v)]=r[2(7-v)]
    // out[4c..4c+3] = (se*ReZ[c], 0.5*ImZ[2047-c], se*ImZ[c], 0.5*ReZ[2047-c]) as fp16
    const float se = (MODE == 0) ? 0.5f : -0.5f;
    H4* __restrict__ o4 = reinterpret_cast<H4*>(out + row * LROW);
#pragma unroll
    for (int u = 0; u < 4; u++) {
        int c = t + 256 * u;  // < 1024
        float2 zc = r[2 * u];
        float2 zr = r[2 * (7 - u) + 1];
        H4 h;
        h.lo = __floats2half2_rn(se * zc.x, 0.5f * zr.y);
        h.hi = __floats2half2_rn(se * zc.y, 0.5f * zr.x);
        o4[c] = h;
    }
#pragma unroll
    for (int v = 0; v < 4; v++) {
        int c = tr + 256 * v;  // < 1024
        float2 zc = r[2 * v + 1];
        float2 zr = r[2 * (7 - v)];
        H4 h;
        h.lo = __floats2half2_rn(se * zc.x, 0.5f * zr.y);
        h.hi = __floats2half2_rn(se * zc.y, 0.5f * zr.x);
        o4[c] = h;
    }
}

// 64x64 half transpose, 128 threads, 4 batched uint4 loads/thread for MLP.
// OUT_FLOAT: convert to fp32 on store (final pass).
template <bool OUT_FLOAT>
__global__ __launch_bounds__(128) void transpose_h_kernel(
    const __half* __restrict__ in, void* __restrict__ out_) {
    __shared__ __half tile[64][65];
    const int x0 = blockIdx.x * 64, y0 = blockIdx.y * 64;
    const int tx = threadIdx.x & 7;   // 0..7
    const int ty = threadIdx.x >> 3;  // 0..15

    uint4 u[4];
#pragma unroll
    for (int j = 0; j < 4; j++) {
        int r = ty + 16 * j;
        u[j] = *reinterpret_cast<const uint4*>(&in[(size_t)(y0 + r) * LROW + x0 + 8 * tx]);
    }
#pragma unroll
    for (int j = 0; j < 4; j++) {
        int r = ty + 16 * j;
        __half tmp[8];
        *reinterpret_cast<uint4*>(tmp) = u[j];
#pragma unroll
        for (int q = 0; q < 8; q++) tile[8 * tx + q][r] = tmp[q];
    }
    __syncthreads();

#pragma unroll
    for (int j = 0; j < 4; j++) {
        int c = ty + 16 * j;  // out row = x0 + c, cols y0 + 8tx .. +7
        if (OUT_FLOAT) {
            float* out = (float*)out_;
            float4 v0, v1;
            v0.x = __half2float(tile[c][8 * tx + 0]);
            v0.y = __half2float(tile[c][8 * tx + 1]);
            v0.z = __half2float(tile[c][8 * tx + 2]);
            v0.w = __half2float(tile[c][8 * tx + 3]);
            v1.x = __half2float(tile[c][8 * tx + 4]);
            v1.y = __half2float(tile[c][8 * tx + 5]);
            v1.z = __half2float(tile[c][8 * tx + 6]);
            v1.w = __half2float(tile[c][8 * tx + 7]);
            float4* o = reinterpret_cast<float4*>(&out[(size_t)(x0 + c) * LROW + y0 + 8 * tx]);
            o[0] = v0;
            o[1] = v1;
        } else {
            __half* out = (__half*)out_;
            __half tmp[8];
#pragma unroll
            for (int q = 0; q < 8; q++) tmp[q] = tile[c][8 * tx + q];
            *reinterpret_cast<uint4*>(&out[(size_t)(x0 + c) * LROW + y0 + 8 * tx]) =
                *reinterpret_cast<uint4*>(tmp);
        }
    }
}

extern "C" void kernel_launch(void* const* d_in, const int* in_sizes, int n_in,
                              void* d_out, int out_size) {
    const float* x = (const float*)d_in[0];
    const float2* expkM = (const float2*)d_in[1];
    const float2* expkN = (const float2*)d_in[2];
    float* out = (float*)d_out;

    __half *bh0, *bh1;
    cudaGetSymbolAddress((void**)&bh0, g_bufh0);
    cudaGetSymbolAddress((void**)&bh1, g_bufh1);

    const size_t smem = (size_t)PADSZ * sizeof(float2);  // 17408 B
    dim3 tg(64, 64);

    init_twiddles_kernel<<<1, 136>>>();
    fft_row_kernel<0, false><<<LROW, FFT_T, smem>>>(x, expkN, bh0);   // t (fp16)
    transpose_h_kernel<false><<<tg, 128>>>(bh0, bh1);                 // t^T (fp16)
    fft_row_kernel<1, true><<<LROW, FFT_T, smem>>>(bh1, expkM, bh0);  // y^T (fp16)
    transpose_h_kernel<true><<<tg, 128>>>(bh0, out);                  // y (fp32)
}